// round 1
// baseline (speedup 1.0000x reference)
#include <cuda_runtime.h>

#define F 96
#define F4 24          // F / 4 (float4 chunks per row)
#define CAPN 50176     // capacity for node count (N = 50000 in this problem)

// Scratch (allocation-free rule: __device__ globals)
__device__ float  g_deg [CAPN];
__device__ float  g_dinv[CAPN];
__device__ float4 g_h   [CAPN * F4];   // layer outputs (reused: h1, then h2a)
__device__ float4 g_agg1[CAPN * F4];   // aggregated hidden (pre-ReLU, bias included)
__device__ float4 g_h2b [CAPN * F4];   // h2b (logstd branch pre-aggregation)

// ---------------------------------------------------------------------------
// Init: zero deg, seed agg1 with b1, seed output halves with b2a / b2b
// ---------------------------------------------------------------------------
__global__ void init_kernel(float* __restrict__ out,
                            const float* __restrict__ b1,
                            const float* __restrict__ b2a,
                            const float* __restrict__ b2b,
                            int N) {
    int i = blockIdx.x * blockDim.x + threadIdx.x;
    int NF = N * F;
    if (i < NF) {
        int c = i % F;
        ((float*)g_agg1)[i] = b1[c];
        out[i]        = b2a[c];
        out[NF + i]   = b2b[c];
    }
    if (i < N) g_deg[i] = 0.f;
}

// ---------------------------------------------------------------------------
// Degree: segment_sum(ones, dst) with warp-uniform aggregation (hub edges
// are contiguous -> whole warps share dst -> one atomic per warp)
// ---------------------------------------------------------------------------
__global__ void deg_kernel(const int* __restrict__ dst, int E) {
    int e = blockIdx.x * blockDim.x + threadIdx.x;
    bool valid = e < E;
    int d = valid ? dst[e] : -1;
    const unsigned full = 0xffffffffu;
    int d0 = __shfl_sync(full, d, 0);
    unsigned bal = __ballot_sync(full, valid && d == d0);
    if (bal == full) {
        if ((threadIdx.x & 31) == 0) atomicAdd(&g_deg[d0], 32.f);
    } else if (valid) {
        atomicAdd(&g_deg[d], 1.f);
    }
}

__global__ void dinv_kernel(int N) {
    int i = blockIdx.x * blockDim.x + threadIdx.x;
    if (i < N) {
        float dg = g_deg[i];
        g_dinv[i] = dg > 0.f ? rsqrtf(fmaxf(dg, 1.f)) : 0.f;
    }
}

// ---------------------------------------------------------------------------
// GEMM: out[N,96] = in[N,96] @ W[96,96]   (optionally ReLU on the input read)
// W cached in smem; x row broadcast via shfl; warp computes 4 rows, 3 cols/lane.
// INSEL: 0 -> xin param, 1 -> g_agg1.   OUTSEL: 0 -> g_h, 1 -> g_h2b.
// ---------------------------------------------------------------------------
template <bool RELU, int INSEL, int OUTSEL>
__global__ void gemm_kernel(const float* __restrict__ xin,
                            const float* __restrict__ W, int N) {
    __shared__ float Ws[F * F];
    for (int i = threadIdx.x; i < F * F; i += blockDim.x) Ws[i] = W[i];
    __syncthreads();

    const float* __restrict__ x = (INSEL == 1) ? (const float*)g_agg1 : xin;
    float* __restrict__ out = (OUTSEL == 1) ? (float*)g_h2b : (float*)g_h;

    const int lane = threadIdx.x & 31;
    const int warp = threadIdx.x >> 5;
    const unsigned full = 0xffffffffu;
    int row0 = (blockIdx.x * 8 + warp) * 4;
    if (row0 >= N) return;

    float xr[4][3];
#pragma unroll
    for (int r = 0; r < 4; r++) {
        int row = row0 + r;
#pragma unroll
        for (int q = 0; q < 3; q++) {
            float v = (row < N) ? x[(size_t)row * F + q * 32 + lane] : 0.f;
            if (RELU) v = fmaxf(v, 0.f);
            xr[r][q] = v;
        }
    }

    float acc[4][3] = {};
#pragma unroll
    for (int q = 0; q < 3; q++) {
#pragma unroll
        for (int kk = 0; kk < 32; kk++) {
            int k = q * 32 + kk;
            float w0 = Ws[k * F + lane];
            float w1 = Ws[k * F + 32 + lane];
            float w2 = Ws[k * F + 64 + lane];
#pragma unroll
            for (int r = 0; r < 4; r++) {
                float xv = __shfl_sync(full, xr[r][q], kk);
                acc[r][0] = fmaf(xv, w0, acc[r][0]);
                acc[r][1] = fmaf(xv, w1, acc[r][1]);
                acc[r][2] = fmaf(xv, w2, acc[r][2]);
            }
        }
    }

#pragma unroll
    for (int r = 0; r < 4; r++) {
        int row = row0 + r;
        if (row < N) {
#pragma unroll
            for (int q = 0; q < 3; q++)
                out[(size_t)row * F + q * 32 + lane] = acc[r][q];
        }
    }
}

// ---------------------------------------------------------------------------
// Scatter pass 1: g_agg1[dst] += g_h[src] * norm
// blockIdx.y = feature chunk (0..23), threads = consecutive edges so that
// hub warps have a uniform dst -> warp-reduce -> one atomic per float.
// ---------------------------------------------------------------------------
__global__ void scatter1_kernel(const int* __restrict__ src,
                                const int* __restrict__ dst, int E) {
    const int chunk = blockIdx.y;
    int e = blockIdx.x * blockDim.x + threadIdx.x;
    bool valid = e < E;
    int s = 0, d = -1;
    float nrm = 0.f;
    if (valid) { s = src[e]; d = dst[e]; nrm = g_dinv[s] * g_dinv[d]; }

    float4 v = make_float4(0.f, 0.f, 0.f, 0.f);
    if (valid) {
        v = g_h[(size_t)s * F4 + chunk];
        v.x *= nrm; v.y *= nrm; v.z *= nrm; v.w *= nrm;
    }

    const unsigned full = 0xffffffffu;
    int d0 = __shfl_sync(full, d, 0);
    unsigned bal = __ballot_sync(full, valid && d == d0);
    float* outp = (float*)g_agg1;
    if (bal == full) {
#pragma unroll
        for (int off = 16; off; off >>= 1) {
            v.x += __shfl_down_sync(full, v.x, off);
            v.y += __shfl_down_sync(full, v.y, off);
            v.z += __shfl_down_sync(full, v.z, off);
            v.w += __shfl_down_sync(full, v.w, off);
        }
        if ((threadIdx.x & 31) == 0) {
            float* p = outp + (size_t)d0 * F + chunk * 4;
            atomicAdd(p + 0, v.x); atomicAdd(p + 1, v.y);
            atomicAdd(p + 2, v.z); atomicAdd(p + 3, v.w);
        }
    } else if (valid) {
        float* p = outp + (size_t)d * F + chunk * 4;
        atomicAdd(p + 0, v.x); atomicAdd(p + 1, v.y);
        atomicAdd(p + 2, v.z); atomicAdd(p + 3, v.w);
    }
}

// ---------------------------------------------------------------------------
// Scatter pass 2 (fused mu + logstd): one edge pass, two feature streams.
// mu   = out[0      .. N*F)  += g_h  [src]*norm  (bias pre-seeded)
// lstd = out[N*F .. 2*N*F)   += g_h2b[src]*norm
// ---------------------------------------------------------------------------
__global__ void scatter2_kernel(const int* __restrict__ src,
                                const int* __restrict__ dst,
                                float* __restrict__ out, int N, int E) {
    const int chunk = blockIdx.y;
    int e = blockIdx.x * blockDim.x + threadIdx.x;
    bool valid = e < E;
    int s = 0, d = -1;
    float nrm = 0.f;
    if (valid) { s = src[e]; d = dst[e]; nrm = g_dinv[s] * g_dinv[d]; }

    float4 va = make_float4(0.f, 0.f, 0.f, 0.f);
    float4 vb = va;
    if (valid) {
        va = g_h  [(size_t)s * F4 + chunk];
        vb = g_h2b[(size_t)s * F4 + chunk];
        va.x *= nrm; va.y *= nrm; va.z *= nrm; va.w *= nrm;
        vb.x *= nrm; vb.y *= nrm; vb.z *= nrm; vb.w *= nrm;
    }

    const size_t NF = (size_t)N * F;
    const unsigned full = 0xffffffffu;
    int d0 = __shfl_sync(full, d, 0);
    unsigned bal = __ballot_sync(full, valid && d == d0);
    if (bal == full) {
#pragma unroll
        for (int off = 16; off; off >>= 1) {
            va.x += __shfl_down_sync(full, va.x, off);
            va.y += __shfl_down_sync(full, va.y, off);
            va.z += __shfl_down_sync(full, va.z, off);
            va.w += __shfl_down_sync(full, va.w, off);
            vb.x += __shfl_down_sync(full, vb.x, off);
            vb.y += __shfl_down_sync(full, vb.y, off);
            vb.z += __shfl_down_sync(full, vb.z, off);
            vb.w += __shfl_down_sync(full, vb.w, off);
        }
        if ((threadIdx.x & 31) == 0) {
            float* pa = out + (size_t)d0 * F + chunk * 4;
            float* pb = pa + NF;
            atomicAdd(pa + 0, va.x); atomicAdd(pa + 1, va.y);
            atomicAdd(pa + 2, va.z); atomicAdd(pa + 3, va.w);
            atomicAdd(pb + 0, vb.x); atomicAdd(pb + 1, vb.y);
            atomicAdd(pb + 2, vb.z); atomicAdd(pb + 3, vb.w);
        }
    } else if (valid) {
        float* pa = out + (size_t)d * F + chunk * 4;
        float* pb = pa + NF;
        atomicAdd(pa + 0, va.x); atomicAdd(pa + 1, va.y);
        atomicAdd(pa + 2, va.z); atomicAdd(pa + 3, va.w);
        atomicAdd(pb + 0, vb.x); atomicAdd(pb + 1, vb.y);
        atomicAdd(pb + 2, vb.z); atomicAdd(pb + 3, vb.w);
    }
}

// ---------------------------------------------------------------------------
// Launch
// inputs: x, W1, b1, W2a, b2a, W2b, b2b, edge_index[2,E]
// output: concat(mu [N,F], logstd [N,F])
// ---------------------------------------------------------------------------
extern "C" void kernel_launch(void* const* d_in, const int* in_sizes, int n_in,
                              void* d_out, int out_size) {
    const float* x   = (const float*)d_in[0];
    const float* W1  = (const float*)d_in[1];
    const float* b1  = (const float*)d_in[2];
    const float* W2a = (const float*)d_in[3];
    const float* b2a = (const float*)d_in[4];
    const float* W2b = (const float*)d_in[5];
    const float* b2b = (const float*)d_in[6];
    const int*   ei  = (const int*)d_in[7];

    const int N = in_sizes[0] / F;
    const int E = in_sizes[7] / 2;
    const int* src = ei;
    const int* dst = ei + E;
    float* out = (float*)d_out;

    const int NF = N * F;
    const int TB = 256;

    dim3 sgrid((E + TB - 1) / TB, F4);

    init_kernel<<<(NF + TB - 1) / TB, TB>>>(out, b1, b2a, b2b, N);
    deg_kernel<<<(E + TB - 1) / TB, TB>>>(dst, E);
    dinv_kernel<<<(N + TB - 1) / TB, TB>>>(N);

    int ggrid = (N + 31) / 32;  // 8 warps * 4 rows per block
    gemm_kernel<false, 0, 0><<<ggrid, TB>>>(x, W1, N);   // h1 -> g_h
    scatter1_kernel<<<sgrid, TB>>>(src, dst, E);          // -> g_agg1 (+b1)
    gemm_kernel<true, 1, 0><<<ggrid, TB>>>(nullptr, W2a, N);  // relu(agg1)@W2a -> g_h
    gemm_kernel<true, 1, 1><<<ggrid, TB>>>(nullptr, W2b, N);  // relu(agg1)@W2b -> g_h2b
    scatter2_kernel<<<sgrid, TB>>>(src, dst, out, N, E);  // -> mu, logstd
}